// round 2
// baseline (speedup 1.0000x reference)
#include <cuda_runtime.h>

#define NN     50000
#define HD_    128
#define EMAX   800000
#define ETMAX  (EMAX + NN)
#define NGRP   64
#define OUTC   64

// ---------------- scratch (static __device__, no allocation) ----------------
__device__ float    g_h[NN * HD_];       // post-GEMM features
__device__ float    g_agg[NN * HD_];     // aggregated output of GAT layer
__device__ float    g_act[NN * HD_];     // activation (input to next layer)
__device__ float    g_als[NN * 4];
__device__ float    g_ald[NN * 4];
__device__ unsigned g_m[NN * 4];         // encoded segment max
__device__ float    g_s[NN * 4];         // softmax denominators
__device__ float    g_ex[(size_t)ETMAX * 4]; // per-edge exp values
__device__ float    g_bn[4 * HD_];       // sum, sumsq, scale, shift
__device__ float    g_pool[NGRP * OUTC];
__device__ float    g_cnt[NGRP];

// ---------------- helpers ----------------
__device__ __forceinline__ unsigned enc_f(float f) {
    unsigned u = __float_as_uint(f);
    return (u & 0x80000000u) ? ~u : (u | 0x80000000u);
}
__device__ __forceinline__ float dec_f(unsigned u) {
    return __uint_as_float((u & 0x80000000u) ? (u ^ 0x80000000u) : ~u);
}

// ---------------- kernels ----------------
__global__ void clear_f(float* p, int n) {
    for (int i = blockIdx.x * blockDim.x + threadIdx.x; i < n; i += gridDim.x * blockDim.x)
        p[i] = 0.f;
}
__global__ void clear_u(unsigned* p, int n) {
    for (int i = blockIdx.x * blockDim.x + threadIdx.x; i < n; i += gridDim.x * blockDim.x)
        p[i] = 0u;  // encodes below any real value
}

// C[r, t] = sum_k A[r,k] * W[k,t];  K fixed = 128, block = M threads, one row per block
__global__ void gemm_rows(const float* __restrict__ A, const float* __restrict__ W,
                          float* __restrict__ C, int M) {
    __shared__ float As[128];
    int r = blockIdx.x;
    int t = threadIdx.x;
    for (int k = t; k < 128; k += blockDim.x) As[k] = A[(size_t)r * 128 + k];
    __syncthreads();
    float acc = 0.f;
#pragma unroll 16
    for (int k = 0; k < 128; k++) acc += As[k] * __ldg(&W[k * M + t]);
    C[(size_t)r * M + t] = acc;
}

// attention logits per (node, head)
__global__ void attn_logits(const float* __restrict__ h, const float* __restrict__ a_s,
                            const float* __restrict__ a_d, float* __restrict__ als,
                            float* __restrict__ ald, int H, int C, int M) {
    int idx = blockIdx.x * blockDim.x + threadIdx.x;
    if (idx >= NN * H) return;
    int n = idx / H, hh = idx - n * H;
    const float* hp = h + (size_t)n * M + hh * C;
    const float* ap = a_s + hh * C;
    const float* dp = a_d + hh * C;
    float s1 = 0.f, s2 = 0.f;
    for (int c = 0; c < C; c++) {
        float v = hp[c];
        s1 += v * __ldg(&ap[c]);
        s2 += v * __ldg(&dp[c]);
    }
    als[idx] = s1;
    ald[idx] = s2;
}

__global__ void init_bias(float* __restrict__ out, const float* __restrict__ b, int M) {
    int total = NN * M;
    for (int i = blockIdx.x * blockDim.x + threadIdx.x; i < total; i += gridDim.x * blockDim.x)
        out[i] = __ldg(&b[i % M]);
}

__global__ void edge_max_k(const int* __restrict__ ei, const float* __restrict__ als,
                           const float* __restrict__ ald, unsigned* __restrict__ m,
                           int H, int ET, int E) {
    int idx = blockIdx.x * blockDim.x + threadIdx.x;
    if (idx >= ET * H) return;
    int e = idx / H, hh = idx - e * H;
    int s, d;
    if (e < E) { s = __ldg(&ei[e]); d = __ldg(&ei[E + e]); }
    else       { s = d = e - E; }
    float v = als[s * H + hh] + ald[d * H + hh];
    v = (v > 0.f) ? v : 0.2f * v;
    atomicMax(&m[d * H + hh], enc_f(v));
}

__global__ void edge_exp_k(const int* __restrict__ ei, const float* __restrict__ als,
                           const float* __restrict__ ald, const unsigned* __restrict__ m,
                           float* __restrict__ ex, float* __restrict__ ssum,
                           int H, int ET, int E) {
    int idx = blockIdx.x * blockDim.x + threadIdx.x;
    if (idx >= ET * H) return;
    int e = idx / H, hh = idx - e * H;
    int s, d;
    if (e < E) { s = __ldg(&ei[e]); d = __ldg(&ei[E + e]); }
    else       { s = d = e - E; }
    float v = als[s * H + hh] + ald[d * H + hh];
    v = (v > 0.f) ? v : 0.2f * v;
    float mm = dec_f(m[d * H + hh]);
    float ev = __expf(v - mm);
    ex[idx] = ev;
    atomicAdd(&ssum[d * H + hh], ev);
}

// warp per edge; each lane handles M/32 channels
__global__ void edge_msg_k(const int* __restrict__ ei, const float* __restrict__ h,
                           const float* __restrict__ ex, const float* __restrict__ ssum,
                           float* __restrict__ out, int H, int logC, int M,
                           int ET, int E) {
    int warp = (blockIdx.x * blockDim.x + threadIdx.x) >> 5;
    int lane = threadIdx.x & 31;
    if (warp >= ET) return;
    int s = 0, d = 0;
    if (lane == 0) {
        if (warp < E) { s = __ldg(&ei[warp]); d = __ldg(&ei[E + warp]); }
        else          { s = d = warp - E; }
    }
    s = __shfl_sync(0xffffffffu, s, 0);
    d = __shfl_sync(0xffffffffu, d, 0);
    for (int k = 0; k < M; k += 32) {
        int ch = k + lane;
        int hh = ch >> logC;
        float alpha = ex[(size_t)warp * H + hh] / (ssum[d * H + hh] + 1e-16f);
        atomicAdd(&out[(size_t)d * M + ch], h[(size_t)s * M + ch] * alpha);
    }
}

__global__ void bn_stats(const float* __restrict__ v, float* __restrict__ bn) {
    int j = threadIdx.x;  // 0..127
    float s = 0.f, q = 0.f;
    for (int r = blockIdx.x; r < NN; r += gridDim.x) {
        float x = v[(size_t)r * HD_ + j];
        s += x;
        q += x * x;
    }
    atomicAdd(&bn[j], s);
    atomicAdd(&bn[HD_ + j], q);
}

__global__ void bn_finalize(float* __restrict__ bn, const float* __restrict__ g,
                            const float* __restrict__ be) {
    int j = threadIdx.x;
    float mu = bn[j] / (float)NN;
    float var = bn[HD_ + j] / (float)NN - mu * mu;
    float sc = __ldg(&g[j]) * rsqrtf(var + 1e-5f);
    bn[2 * HD_ + j] = sc;
    bn[3 * HD_ + j] = __ldg(&be[j]) - mu * sc;
}

__global__ void bn_apply_elu(const float* __restrict__ v, const float* __restrict__ bn,
                             float* __restrict__ out) {
    int total = NN * HD_;
    for (int i = blockIdx.x * blockDim.x + threadIdx.x; i < total; i += gridDim.x * blockDim.x) {
        int j = i & (HD_ - 1);
        float y = v[i] * bn[2 * HD_ + j] + bn[3 * HD_ + j];
        out[i] = (y > 0.f) ? y : expm1f(y);
    }
}

__global__ void pool_acc(const float* __restrict__ v, const int* __restrict__ bid,
                         float* __restrict__ pool) {
    int idx = blockIdx.x * blockDim.x + threadIdx.x;
    if (idx >= NN * OUTC) return;
    int n = idx >> 6, j = idx & 63;
    int g = __ldg(&bid[n]);
    atomicAdd(&pool[g * OUTC + j], v[(size_t)n * OUTC + j]);
}

__global__ void cnt_acc(const int* __restrict__ bid, float* __restrict__ cnt) {
    int n = blockIdx.x * blockDim.x + threadIdx.x;
    if (n >= NN) return;
    atomicAdd(&cnt[__ldg(&bid[n])], 1.f);
}

__global__ void pool_fin(const float* __restrict__ pool, const float* __restrict__ cnt,
                         float* __restrict__ out) {
    int i = blockIdx.x * blockDim.x + threadIdx.x;
    if (i >= NGRP * OUTC) return;
    float c = cnt[i >> 6];
    out[i] = pool[i] / fmaxf(c, 1.f);
}

// ---------------- host ----------------
static inline int ceil_div(int a, int b) { return (a + b - 1) / b; }

extern "C" void kernel_launch(void* const* d_in, const int* in_sizes, int n_in,
                              void* d_out, int out_size) {
    const float* x   = (const float*)d_in[0];
    const int*   ei  = (const int*)d_in[1];   // harness delivers int64 source as int32
    const int*   bid = (const int*)d_in[2];
    const float *W[4], *As[4], *Ad[4], *B[4];
    for (int i = 0; i < 4; i++) {
        W[i]  = (const float*)d_in[3 + 4 * i];
        As[i] = (const float*)d_in[4 + 4 * i];
        Ad[i] = (const float*)d_in[5 + 4 * i];
        B[i]  = (const float*)d_in[6 + 4 * i];
    }
    const float *G[3], *Be[3];
    for (int i = 0; i < 3; i++) {
        G[i]  = (const float*)d_in[19 + 2 * i];
        Be[i] = (const float*)d_in[20 + 2 * i];
    }
    int E  = in_sizes[1] / 2;
    int ET = E + NN;

    float *h_, *agg_, *act_, *als_, *ald_, *s_, *ex_, *bn_, *pool_, *cnt_;
    unsigned* m_;
    cudaGetSymbolAddress((void**)&h_,    g_h);
    cudaGetSymbolAddress((void**)&agg_,  g_agg);
    cudaGetSymbolAddress((void**)&act_,  g_act);
    cudaGetSymbolAddress((void**)&als_,  g_als);
    cudaGetSymbolAddress((void**)&ald_,  g_ald);
    cudaGetSymbolAddress((void**)&m_,    g_m);
    cudaGetSymbolAddress((void**)&s_,    g_s);
    cudaGetSymbolAddress((void**)&ex_,   g_ex);
    cudaGetSymbolAddress((void**)&bn_,   g_bn);
    cudaGetSymbolAddress((void**)&pool_, g_pool);
    cudaGetSymbolAddress((void**)&cnt_,  g_cnt);

    const int TB = 256;

    for (int l = 0; l < 4; l++) {
        int H    = (l < 3) ? 4 : 1;
        int C    = (l < 3) ? 32 : 64;
        int logC = (l < 3) ? 5 : 6;
        int M    = H * C;  // 128 or 64
        const float* in = (l == 0) ? x : act_;

        gemm_rows<<<NN, M>>>(in, W[l], h_, M);
        attn_logits<<<ceil_div(NN * H, TB), TB>>>(h_, As[l], Ad[l], als_, ald_, H, C, M);
        clear_u<<<256, TB>>>(m_, NN * H);
        clear_f<<<256, TB>>>(s_, NN * H);
        init_bias<<<512, TB>>>(agg_, B[l], M);
        edge_max_k<<<ceil_div(ET * H, TB), TB>>>(ei, als_, ald_, m_, H, ET, E);
        edge_exp_k<<<ceil_div(ET * H, TB), TB>>>(ei, als_, ald_, m_, ex_, s_, H, ET, E);
        edge_msg_k<<<ceil_div(ET * 32, TB), TB>>>(ei, h_, ex_, s_, agg_, H, logC, M, ET, E);

        if (l < 3) {
            clear_f<<<1, 256>>>(bn_, 2 * HD_);
            bn_stats<<<256, HD_>>>(agg_, bn_);
            bn_finalize<<<1, HD_>>>(bn_, G[l], Be[l]);
            bn_apply_elu<<<512, TB>>>(agg_, bn_, act_);
        }
    }

    // global mean pool over 64 graphs, input = agg_ [NN, 64]
    clear_f<<<1, 256>>>(pool_, NGRP * OUTC);
    clear_f<<<1, NGRP>>>(cnt_, NGRP);
    pool_acc<<<ceil_div(NN * OUTC, TB), TB>>>(agg_, bid, pool_);
    cnt_acc<<<ceil_div(NN, TB), TB>>>(bid, cnt_);
    pool_fin<<<ceil_div(NGRP * OUTC, TB), TB>>>(pool_, cnt_, (float*)d_out);
}

// round 3
// speedup vs baseline: 2.3509x; 2.3509x over previous
#include <cuda_runtime.h>

#define NN     50000
#define HD_    128
#define EMAX   800000
#define ETMAX  (EMAX + NN)
#define NGRP   64
#define OUTC   64

// ---------------- scratch (static __device__, no allocation) ----------------
__device__ float  g_h[NN * HD_];
__device__ float  g_agg[NN * HD_];
__device__ float  g_act[NN * HD_];
__device__ float  g_als[NN * 4];
__device__ float  g_ald[NN * 4];
__device__ float4 g_ex4[ETMAX];          // per-CSR-slot exp values (4 heads)
__device__ int    g_deg[NN];
__device__ int    g_roff[NN + 1];
__device__ int    g_cur[NN];
__device__ int    g_csrc[ETMAX];
__device__ float  g_bn[4 * HD_];
__device__ float  g_pool[NGRP * OUTC];
__device__ float  g_cnt[NGRP];

static inline int ceil_div(int a, int b) { return (a + b - 1) / b; }

// ---------------- misc ----------------
__global__ void clear_f(float* p, int n) {
    for (int i = blockIdx.x * blockDim.x + threadIdx.x; i < n; i += gridDim.x * blockDim.x)
        p[i] = 0.f;
}
__global__ void clear_i(int* p, int n) {
    for (int i = blockIdx.x * blockDim.x + threadIdx.x; i < n; i += gridDim.x * blockDim.x)
        p[i] = 0;
}

// ---------------- CSR build (once per launch, reused by all 4 layers) -------
__global__ void hist_k(const int* __restrict__ ei, int* __restrict__ deg, int E, int ET) {
    for (int e = blockIdx.x * blockDim.x + threadIdx.x; e < ET; e += gridDim.x * blockDim.x) {
        int d = (e < E) ? __ldg(&ei[E + e]) : (e - E);
        atomicAdd(&deg[d], 1);
    }
}

__global__ void scan_k(const int* __restrict__ deg, int* __restrict__ roff,
                       int* __restrict__ cur) {
    __shared__ int ssum[1024];
    int tid = threadIdx.x;
    const int CH = (NN + 1023) / 1024;
    int base = tid * CH;
    int s = 0;
    for (int i = 0; i < CH; i++) {
        int n = base + i;
        if (n < NN) s += deg[n];
    }
    ssum[tid] = s;
    __syncthreads();
    for (int off = 1; off < 1024; off <<= 1) {
        int v = 0;
        if (tid >= off) v = ssum[tid - off];
        __syncthreads();
        if (tid >= off) ssum[tid] += v;
        __syncthreads();
    }
    int run = (tid == 0) ? 0 : ssum[tid - 1];
    for (int i = 0; i < CH; i++) {
        int n = base + i;
        if (n < NN) {
            roff[n] = run;
            cur[n]  = run;
            run += deg[n];
        }
    }
    if (tid == 1023) roff[NN] = ssum[1023];
}

__global__ void scatter_k(const int* __restrict__ ei, int* __restrict__ cur,
                          int* __restrict__ csrc, int E, int ET) {
    for (int e = blockIdx.x * blockDim.x + threadIdx.x; e < ET; e += gridDim.x * blockDim.x) {
        int s, d;
        if (e < E) { s = __ldg(&ei[e]); d = __ldg(&ei[E + e]); }
        else       { s = d = e - E; }
        int pos = atomicAdd(&cur[d], 1);
        csrc[pos] = s;
    }
}

// ---------------- GEMM: C[rows, M] = A[rows, 128] @ W[128, M] ----------------
// blockDim = M threads; 32 rows per block; thread -> (rowgroup rg of 8, colgroup cg of 4)
template <int M>
__global__ void gemm_k(const float* __restrict__ A, const float* __restrict__ W,
                       float* __restrict__ C, int rows) {
    __shared__ float xs[32 * 128];
    int row0 = blockIdx.x * 32;
    int t = threadIdx.x;
    const int CG = M / 4;
    int cg = t % CG;
    int rg = t / CG;   // 0..3

    for (int i = t; i < 32 * 32; i += M) {  // 32 rows x 32 float4
        int r = i >> 5, c4 = i & 31;
        float4 v = make_float4(0.f, 0.f, 0.f, 0.f);
        if (row0 + r < rows) v = *(const float4*)&A[(size_t)(row0 + r) * 128 + c4 * 4];
        *(float4*)&xs[r * 128 + c4 * 4] = v;
    }
    __syncthreads();

    float acc[8][4];
#pragma unroll
    for (int r = 0; r < 8; r++)
#pragma unroll
        for (int j = 0; j < 4; j++) acc[r][j] = 0.f;

#pragma unroll 4
    for (int k = 0; k < 128; k++) {
        float4 w = __ldg((const float4*)&W[k * M + cg * 4]);
#pragma unroll
        for (int r = 0; r < 8; r++) {
            float x = xs[(rg * 8 + r) * 128 + k];
            acc[r][0] += x * w.x;
            acc[r][1] += x * w.y;
            acc[r][2] += x * w.z;
            acc[r][3] += x * w.w;
        }
    }
#pragma unroll
    for (int r = 0; r < 8; r++) {
        int rr = row0 + rg * 8 + r;
        if (rr < rows) {
            float4 o = make_float4(acc[r][0], acc[r][1], acc[r][2], acc[r][3]);
            *(float4*)&C[(size_t)rr * M + cg * 4] = o;
        }
    }
}

// ---------------- attention logits ----------------
template <int H, int C>
__global__ void attn_k(const float* __restrict__ h, const float* __restrict__ a_s,
                       const float* __restrict__ a_d, float* __restrict__ als,
                       float* __restrict__ ald) {
    int idx = blockIdx.x * blockDim.x + threadIdx.x;
    if (idx >= NN * H) return;
    int n = idx / H, hh = idx % H;
    const float4* hp = (const float4*)(h + (size_t)n * (H * C) + hh * C);
    const float4* ap = (const float4*)(a_s + hh * C);
    const float4* dp = (const float4*)(a_d + hh * C);
    float s1 = 0.f, s2 = 0.f;
#pragma unroll
    for (int c = 0; c < C / 4; c++) {
        float4 v = hp[c];
        float4 a = __ldg(&ap[c]);
        float4 d = __ldg(&dp[c]);
        s1 += v.x * a.x + v.y * a.y + v.z * a.z + v.w * a.w;
        s2 += v.x * d.x + v.y * d.y + v.z * d.z + v.w * d.w;
    }
    als[idx] = s1;
    ald[idx] = s2;
}

// ---------------- fused per-node GAT aggregation (warp per node) ------------
__device__ __forceinline__ float lrelu(float v) { return v > 0.f ? v : 0.2f * v; }

template <int H, int M>
__global__ void aggregate_k(const int* __restrict__ roff, const int* __restrict__ csrc,
                            const float* __restrict__ h, const float* __restrict__ als,
                            const float* __restrict__ ald, const float* __restrict__ bias,
                            float4* __restrict__ ex4, float* __restrict__ out) {
    int node = (blockIdx.x * blockDim.x + threadIdx.x) >> 5;
    int lane = threadIdx.x & 31;
    if (node >= NN) return;
    int beg = roff[node], end = roff[node + 1];

    float ad0, ad1 = 0.f, ad2 = 0.f, ad3 = 0.f;
    if (H == 4) {
        float4 t = *(const float4*)&ald[node * 4];
        ad0 = t.x; ad1 = t.y; ad2 = t.z; ad3 = t.w;
    } else {
        ad0 = ald[node];
    }

    // phase 1: per-head max
    float m0 = -1e30f, m1 = -1e30f, m2 = -1e30f, m3 = -1e30f;
    for (int j = beg + lane; j < end; j += 32) {
        int s = csrc[j];
        if (H == 4) {
            float4 a = *(const float4*)&als[s * 4];
            m0 = fmaxf(m0, lrelu(a.x + ad0));
            m1 = fmaxf(m1, lrelu(a.y + ad1));
            m2 = fmaxf(m2, lrelu(a.z + ad2));
            m3 = fmaxf(m3, lrelu(a.w + ad3));
        } else {
            m0 = fmaxf(m0, lrelu(als[s] + ad0));
        }
    }
#pragma unroll
    for (int o = 16; o; o >>= 1) {
        m0 = fmaxf(m0, __shfl_xor_sync(0xffffffffu, m0, o));
        if (H == 4) {
            m1 = fmaxf(m1, __shfl_xor_sync(0xffffffffu, m1, o));
            m2 = fmaxf(m2, __shfl_xor_sync(0xffffffffu, m2, o));
            m3 = fmaxf(m3, __shfl_xor_sync(0xffffffffu, m3, o));
        }
    }

    // phase 2: exp, store, sum
    float s0 = 0.f, s1 = 0.f, s2 = 0.f, s3 = 0.f;
    for (int j = beg + lane; j < end; j += 32) {
        int s = csrc[j];
        float4 e;
        if (H == 4) {
            float4 a = *(const float4*)&als[s * 4];
            e.x = __expf(lrelu(a.x + ad0) - m0);
            e.y = __expf(lrelu(a.y + ad1) - m1);
            e.z = __expf(lrelu(a.z + ad2) - m2);
            e.w = __expf(lrelu(a.w + ad3) - m3);
            s0 += e.x; s1 += e.y; s2 += e.z; s3 += e.w;
        } else {
            e.x = __expf(lrelu(als[s] + ad0) - m0);
            e.y = e.z = e.w = 0.f;
            s0 += e.x;
        }
        ex4[j] = e;
    }
#pragma unroll
    for (int o = 16; o; o >>= 1) {
        s0 += __shfl_xor_sync(0xffffffffu, s0, o);
        if (H == 4) {
            s1 += __shfl_xor_sync(0xffffffffu, s1, o);
            s2 += __shfl_xor_sync(0xffffffffu, s2, o);
            s3 += __shfl_xor_sync(0xffffffffu, s3, o);
        }
    }
    float r0 = 1.f / (s0 + 1e-16f);
    float r1 = (H == 4) ? 1.f / (s1 + 1e-16f) : 0.f;
    float r2 = (H == 4) ? 1.f / (s2 + 1e-16f) : 0.f;
    float r3 = (H == 4) ? 1.f / (s3 + 1e-16f) : 0.f;

    // phase 3: channel-parallel accumulation (no atomics)
    float a0 = 0.f, a1 = 0.f, a2 = 0.f, a3 = 0.f;
    for (int j = beg; j < end; j++) {
        int s = csrc[j];            // uniform across warp -> broadcast load
        float4 e = ex4[j];
        const float* hp = h + (size_t)s * M;
        if (H == 4) {
            a0 += hp[lane]      * e.x;
            a1 += hp[lane + 32] * e.y;
            a2 += hp[lane + 64] * e.z;
            a3 += hp[lane + 96] * e.w;
        } else {
            a0 += hp[lane]      * e.x;
            a1 += hp[lane + 32] * e.x;
        }
    }
    float* op = out + (size_t)node * M;
    if (H == 4) {
        op[lane]      = a0 * r0 + __ldg(&bias[lane]);
        op[lane + 32] = a1 * r1 + __ldg(&bias[lane + 32]);
        op[lane + 64] = a2 * r2 + __ldg(&bias[lane + 64]);
        op[lane + 96] = a3 * r3 + __ldg(&bias[lane + 96]);
    } else {
        op[lane]      = a0 * r0 + __ldg(&bias[lane]);
        op[lane + 32] = a1 * r0 + __ldg(&bias[lane + 32]);
    }
}

// ---------------- batchnorm + ELU ----------------
__global__ void bn_stats(const float* __restrict__ v, float* __restrict__ bn) {
    int j = threadIdx.x;  // 0..127
    float s = 0.f, q = 0.f;
    for (int r = blockIdx.x; r < NN; r += gridDim.x) {
        float x = v[(size_t)r * HD_ + j];
        s += x;
        q += x * x;
    }
    atomicAdd(&bn[j], s);
    atomicAdd(&bn[HD_ + j], q);
}

__global__ void bn_finalize(float* __restrict__ bn, const float* __restrict__ g,
                            const float* __restrict__ be) {
    int j = threadIdx.x;
    float mu = bn[j] / (float)NN;
    float var = bn[HD_ + j] / (float)NN - mu * mu;
    float sc = __ldg(&g[j]) * rsqrtf(var + 1e-5f);
    bn[2 * HD_ + j] = sc;
    bn[3 * HD_ + j] = __ldg(&be[j]) - mu * sc;
}

__global__ void bn_apply_elu(const float* __restrict__ v, const float* __restrict__ bn,
                             float* __restrict__ out) {
    int total = NN * HD_;
    for (int i = blockIdx.x * blockDim.x + threadIdx.x; i < total; i += gridDim.x * blockDim.x) {
        int j = i & (HD_ - 1);
        float y = v[i] * bn[2 * HD_ + j] + bn[3 * HD_ + j];
        out[i] = (y > 0.f) ? y : expm1f(y);
    }
}

// ---------------- global mean pool ----------------
__global__ void pool_acc(const float* __restrict__ v, const int* __restrict__ bid,
                         float* __restrict__ pool) {
    int idx = blockIdx.x * blockDim.x + threadIdx.x;
    if (idx >= NN * OUTC) return;
    int n = idx >> 6, j = idx & 63;
    int g = __ldg(&bid[n]);
    atomicAdd(&pool[g * OUTC + j], v[(size_t)n * OUTC + j]);
}

__global__ void cnt_acc(const int* __restrict__ bid, float* __restrict__ cnt) {
    int n = blockIdx.x * blockDim.x + threadIdx.x;
    if (n >= NN) return;
    atomicAdd(&cnt[__ldg(&bid[n])], 1.f);
}

__global__ void pool_fin(const float* __restrict__ pool, const float* __restrict__ cnt,
                         float* __restrict__ out) {
    int i = blockIdx.x * blockDim.x + threadIdx.x;
    if (i >= NGRP * OUTC) return;
    float c = cnt[i >> 6];
    out[i] = pool[i] / fmaxf(c, 1.f);
}

// ---------------- host ----------------
extern "C" void kernel_launch(void* const* d_in, const int* in_sizes, int n_in,
                              void* d_out, int out_size) {
    const float* x   = (const float*)d_in[0];
    const int*   ei  = (const int*)d_in[1];
    const int*   bid = (const int*)d_in[2];
    const float *W[4], *As[4], *Ad[4], *B[4];
    for (int i = 0; i < 4; i++) {
        W[i]  = (const float*)d_in[3 + 4 * i];
        As[i] = (const float*)d_in[4 + 4 * i];
        Ad[i] = (const float*)d_in[5 + 4 * i];
        B[i]  = (const float*)d_in[6 + 4 * i];
    }
    const float *G[3], *Be[3];
    for (int i = 0; i < 3; i++) {
        G[i]  = (const float*)d_in[19 + 2 * i];
        Be[i] = (const float*)d_in[20 + 2 * i];
    }
    int E  = in_sizes[1] / 2;
    int ET = E + NN;

    float *h_, *agg_, *act_, *als_, *ald_, *bn_, *pool_, *cnt_;
    float4* ex4_;
    int *deg_, *roff_, *cur_, *csrc_;
    cudaGetSymbolAddress((void**)&h_,    g_h);
    cudaGetSymbolAddress((void**)&agg_,  g_agg);
    cudaGetSymbolAddress((void**)&act_,  g_act);
    cudaGetSymbolAddress((void**)&als_,  g_als);
    cudaGetSymbolAddress((void**)&ald_,  g_ald);
    cudaGetSymbolAddress((void**)&ex4_,  g_ex4);
    cudaGetSymbolAddress((void**)&deg_,  g_deg);
    cudaGetSymbolAddress((void**)&roff_, g_roff);
    cudaGetSymbolAddress((void**)&cur_,  g_cur);
    cudaGetSymbolAddress((void**)&csrc_, g_csrc);
    cudaGetSymbolAddress((void**)&bn_,   g_bn);
    cudaGetSymbolAddress((void**)&pool_, g_pool);
    cudaGetSymbolAddress((void**)&cnt_,  g_cnt);

    const int TB = 256;

    // ---- CSR build (topology shared by all layers) ----
    clear_i<<<128, TB>>>(deg_, NN);
    hist_k<<<512, TB>>>(ei, deg_, E, ET);
    scan_k<<<1, 1024>>>(deg_, roff_, cur_);
    scatter_k<<<512, TB>>>(ei, cur_, csrc_, E, ET);

    // ---- layers ----
    for (int l = 0; l < 4; l++) {
        const float* in = (l == 0) ? x : act_;
        if (l < 3) {
            gemm_k<128><<<ceil_div(NN, 32), 128>>>(in, W[l], h_, NN);
            attn_k<4, 32><<<ceil_div(NN * 4, TB), TB>>>(h_, As[l], Ad[l], als_, ald_);
            aggregate_k<4, 128><<<ceil_div(NN * 32, TB), TB>>>(roff_, csrc_, h_, als_, ald_,
                                                               B[l], ex4_, agg_);
            clear_f<<<1, 256>>>(bn_, 2 * HD_);
            bn_stats<<<256, HD_>>>(agg_, bn_);
            bn_finalize<<<1, HD_>>>(bn_, G[l], Be[l]);
            bn_apply_elu<<<512, TB>>>(agg_, bn_, act_);
        } else {
            gemm_k<64><<<ceil_div(NN, 32), 64>>>(in, W[l], h_, NN);
            attn_k<1, 64><<<ceil_div(NN, TB), TB>>>(h_, As[l], Ad[l], als_, ald_);
            aggregate_k<1, 64><<<ceil_div(NN * 32, TB), TB>>>(roff_, csrc_, h_, als_, ald_,
                                                              B[l], ex4_, agg_);
        }
    }

    // ---- global mean pool ----
    clear_f<<<1, 256>>>(pool_, NGRP * OUTC);
    clear_f<<<1, NGRP>>>(cnt_, NGRP);
    pool_acc<<<ceil_div(NN * OUTC, TB), TB>>>(agg_, bid, pool_);
    cnt_acc<<<ceil_div(NN, TB), TB>>>(bid, cnt_);
    pool_fin<<<ceil_div(NGRP * OUTC, TB), TB>>>(pool_, cnt_, (float*)d_out);
}

// round 4
// speedup vs baseline: 3.0754x; 1.3082x over previous
#include <cuda_runtime.h>

#define NN     50000
#define HD_    128
#define EMAX   800000
#define ETMAX  (EMAX + NN)
#define NGRP   64
#define OUTC   64

// ---------------- scratch ----------------
__device__ float  g_h[NN * HD_];
__device__ float  g_agg[NN * HD_];
__device__ float  g_als[NN * 4];
__device__ float  g_ald[NN * 4];
__device__ float4 g_ex4[ETMAX];
__device__ int    g_deg[NN];
__device__ int    g_roff[NN + 1];
__device__ int    g_cur[NN];
__device__ int    g_csrc[ETMAX];
__device__ float  g_bn[4 * HD_];   // [0:128) sum, [128:256) sumsq, [256:384) scale, [384:512) shift
__device__ float  g_pool[NGRP * OUTC];
__device__ float  g_cnt[NGRP];

static inline int ceil_div(int a, int b) { return (a + b - 1) / b; }

__device__ __forceinline__ float lrelu(float v) { return v > 0.f ? v : 0.2f * v; }
__device__ __forceinline__ float elu_f(float y) { return y > 0.f ? y : __expf(y) - 1.f; }

// ---------------- misc ----------------
__global__ void clear_f(float* p, int n) {
    for (int i = blockIdx.x * blockDim.x + threadIdx.x; i < n; i += gridDim.x * blockDim.x)
        p[i] = 0.f;
}
__global__ void clear_i(int* p, int n) {
    for (int i = blockIdx.x * blockDim.x + threadIdx.x; i < n; i += gridDim.x * blockDim.x)
        p[i] = 0;
}

// ---------------- CSR build ----------------
__global__ void hist_k(const int* __restrict__ ei, int* __restrict__ deg, int E, int ET) {
    for (int e = blockIdx.x * blockDim.x + threadIdx.x; e < ET; e += gridDim.x * blockDim.x) {
        int d = (e < E) ? __ldg(&ei[E + e]) : (e - E);
        atomicAdd(&deg[d], 1);
    }
}

__global__ void scan_k(const int* __restrict__ deg, int* __restrict__ roff,
                       int* __restrict__ cur) {
    __shared__ int ssum[1024];
    int tid = threadIdx.x;
    const int CH = (NN + 1023) / 1024;
    int base = tid * CH;
    int s = 0;
    for (int i = 0; i < CH; i++) {
        int n = base + i;
        if (n < NN) s += deg[n];
    }
    ssum[tid] = s;
    __syncthreads();
    for (int off = 1; off < 1024; off <<= 1) {
        int v = 0;
        if (tid >= off) v = ssum[tid - off];
        __syncthreads();
        if (tid >= off) ssum[tid] += v;
        __syncthreads();
    }
    int run = (tid == 0) ? 0 : ssum[tid - 1];
    for (int i = 0; i < CH; i++) {
        int n = base + i;
        if (n < NN) {
            roff[n] = run;
            cur[n]  = run;
            run += deg[n];
        }
    }
    if (tid == 1023) roff[NN] = ssum[1023];
}

__global__ void scatter_k(const int* __restrict__ ei, int* __restrict__ cur,
                          int* __restrict__ csrc, int E, int ET) {
    for (int e = blockIdx.x * blockDim.x + threadIdx.x; e < ET; e += gridDim.x * blockDim.x) {
        int s, d;
        if (e < E) { s = __ldg(&ei[e]); d = __ldg(&ei[E + e]); }
        else       { s = d = e - E; }
        int pos = atomicAdd(&cur[d], 1);
        csrc[pos] = s;
    }
}

// ---------------- GEMM (optionally fusing BN affine + ELU on the input) -----
template <int M, bool BNIN>
__global__ void gemm_k(const float* __restrict__ A, const float* __restrict__ W,
                       const float* __restrict__ bn, float* __restrict__ C, int rows) {
    __shared__ float xs[32 * 128];
    int row0 = blockIdx.x * 32;
    int t = threadIdx.x;
    const int CG = M / 4;
    int cg = t % CG;
    int rg = t / CG;   // 0..3

    for (int i = t; i < 32 * 32; i += M) {
        int r = i >> 5, c4 = i & 31;
        float4 v = make_float4(0.f, 0.f, 0.f, 0.f);
        if (row0 + r < rows) {
            v = *(const float4*)&A[(size_t)(row0 + r) * 128 + c4 * 4];
            if (BNIN) {
                float4 sc = *(const float4*)&bn[2 * HD_ + c4 * 4];
                float4 sh = *(const float4*)&bn[3 * HD_ + c4 * 4];
                v.x = elu_f(v.x * sc.x + sh.x);
                v.y = elu_f(v.y * sc.y + sh.y);
                v.z = elu_f(v.z * sc.z + sh.z);
                v.w = elu_f(v.w * sc.w + sh.w);
            }
        }
        *(float4*)&xs[r * 128 + c4 * 4] = v;
    }
    __syncthreads();

    float acc[8][4];
#pragma unroll
    for (int r = 0; r < 8; r++)
#pragma unroll
        for (int j = 0; j < 4; j++) acc[r][j] = 0.f;

    const float4* xs4 = (const float4*)xs;
#pragma unroll 4
    for (int k4 = 0; k4 < 32; k4++) {
        float4 w0 = __ldg((const float4*)&W[(size_t)(k4 * 4 + 0) * M + cg * 4]);
        float4 w1 = __ldg((const float4*)&W[(size_t)(k4 * 4 + 1) * M + cg * 4]);
        float4 w2 = __ldg((const float4*)&W[(size_t)(k4 * 4 + 2) * M + cg * 4]);
        float4 w3 = __ldg((const float4*)&W[(size_t)(k4 * 4 + 3) * M + cg * 4]);
#pragma unroll
        for (int r = 0; r < 8; r++) {
            float4 xv = xs4[(rg * 8 + r) * 32 + k4];
            acc[r][0] += xv.x * w0.x + xv.y * w1.x + xv.z * w2.x + xv.w * w3.x;
            acc[r][1] += xv.x * w0.y + xv.y * w1.y + xv.z * w2.y + xv.w * w3.y;
            acc[r][2] += xv.x * w0.z + xv.y * w1.z + xv.z * w2.z + xv.w * w3.z;
            acc[r][3] += xv.x * w0.w + xv.y * w1.w + xv.z * w2.w + xv.w * w3.w;
        }
    }
#pragma unroll
    for (int r = 0; r < 8; r++) {
        int rr = row0 + rg * 8 + r;
        if (rr < rows) {
            float4 o = make_float4(acc[r][0], acc[r][1], acc[r][2], acc[r][3]);
            *(float4*)&C[(size_t)rr * M + cg * 4] = o;
        }
    }
}

// ---------------- attention logits ----------------
template <int H, int C>
__global__ void attn_k(const float* __restrict__ h, const float* __restrict__ a_s,
                       const float* __restrict__ a_d, float* __restrict__ als,
                       float* __restrict__ ald) {
    int idx = blockIdx.x * blockDim.x + threadIdx.x;
    if (idx >= NN * H) return;
    int n = idx / H, hh = idx % H;
    const float4* hp = (const float4*)(h + (size_t)n * (H * C) + hh * C);
    const float4* ap = (const float4*)(a_s + hh * C);
    const float4* dp = (const float4*)(a_d + hh * C);
    float s1 = 0.f, s2 = 0.f;
#pragma unroll
    for (int c = 0; c < C / 4; c++) {
        float4 v = hp[c];
        float4 a = __ldg(&ap[c]);
        float4 d = __ldg(&dp[c]);
        s1 += v.x * a.x + v.y * a.y + v.z * a.z + v.w * a.w;
        s2 += v.x * d.x + v.y * d.y + v.z * d.z + v.w * d.w;
    }
    als[idx] = s1;
    ald[idx] = s2;
}

// ---------------- fused per-node GAT aggregation (warp per node) ------------
// H==4: M=128, one float4 per lane covers the row; head = lane>>3.
// H==1: M=64, one float2 per lane.
// STATS: accumulate BN sum/sumsq of the output into bn[0:256) via smem reduce.
template <int H, int M, bool STATS>
__global__ void aggregate_k(const int* __restrict__ roff, const int* __restrict__ csrc,
                            const float* __restrict__ h, const float* __restrict__ als,
                            const float* __restrict__ ald, const float* __restrict__ bias,
                            float4* __restrict__ ex4, float* __restrict__ out,
                            float* __restrict__ bn) {
    __shared__ float sred[2 * HD_];
    int t = threadIdx.x;
    if (STATS) {
        if (t < 2 * HD_) sred[t] = 0.f;
        __syncthreads();
    }
    int node = (blockIdx.x * blockDim.x + t) >> 5;
    int lane = t & 31;
    bool active = (node < NN);
    int beg = 0, end = 0;
    if (active) { beg = roff[node]; end = roff[node + 1]; }

    float ad0 = 0.f, ad1 = 0.f, ad2 = 0.f, ad3 = 0.f;
    if (active) {
        if (H == 4) {
            float4 tt = *(const float4*)&ald[node * 4];
            ad0 = tt.x; ad1 = tt.y; ad2 = tt.z; ad3 = tt.w;
        } else {
            ad0 = ald[node];
        }
    }

    // phase 1: per-head max
    float m0 = -1e30f, m1 = -1e30f, m2 = -1e30f, m3 = -1e30f;
    for (int j = beg + lane; j < end; j += 32) {
        int s = csrc[j];
        if (H == 4) {
            float4 a = *(const float4*)&als[s * 4];
            m0 = fmaxf(m0, lrelu(a.x + ad0));
            m1 = fmaxf(m1, lrelu(a.y + ad1));
            m2 = fmaxf(m2, lrelu(a.z + ad2));
            m3 = fmaxf(m3, lrelu(a.w + ad3));
        } else {
            m0 = fmaxf(m0, lrelu(als[s] + ad0));
        }
    }
#pragma unroll
    for (int o = 16; o; o >>= 1) {
        m0 = fmaxf(m0, __shfl_xor_sync(0xffffffffu, m0, o));
        if (H == 4) {
            m1 = fmaxf(m1, __shfl_xor_sync(0xffffffffu, m1, o));
            m2 = fmaxf(m2, __shfl_xor_sync(0xffffffffu, m2, o));
            m3 = fmaxf(m3, __shfl_xor_sync(0xffffffffu, m3, o));
        }
    }

    // phase 2: exp, store, sum
    float s0 = 0.f, s1 = 0.f, s2 = 0.f, s3 = 0.f;
    for (int j = beg + lane; j < end; j += 32) {
        int s = csrc[j];
        float4 e;
        if (H == 4) {
            float4 a = *(const float4*)&als[s * 4];
            e.x = __expf(lrelu(a.x + ad0) - m0);
            e.y = __expf(lrelu(a.y + ad1) - m1);
            e.z = __expf(lrelu(a.z + ad2) - m2);
            e.w = __expf(lrelu(a.w + ad3) - m3);
            s0 += e.x; s1 += e.y; s2 += e.z; s3 += e.w;
        } else {
            e.x = __expf(lrelu(als[s] + ad0) - m0);
            e.y = e.z = e.w = 0.f;
            s0 += e.x;
        }
        ex4[j] = e;
    }
#pragma unroll
    for (int o = 16; o; o >>= 1) {
        s0 += __shfl_xor_sync(0xffffffffu, s0, o);
        if (H == 4) {
            s1 += __shfl_xor_sync(0xffffffffu, s1, o);
            s2 += __shfl_xor_sync(0xffffffffu, s2, o);
            s3 += __shfl_xor_sync(0xffffffffu, s3, o);
        }
    }

    if (H == 4) {
        float r0 = 1.f / (s0 + 1e-16f), r1 = 1.f / (s1 + 1e-16f);
        float r2 = 1.f / (s2 + 1e-16f), r3 = 1.f / (s3 + 1e-16f);
        // per-lane normalizer: head = lane>>3
        float rv = lane < 16 ? (lane < 8 ? r0 : r1) : (lane < 24 ? r2 : r3);

        float4 acc = make_float4(0.f, 0.f, 0.f, 0.f);
        int j = beg;
        for (; j + 2 <= end; j += 2) {
            int sA = csrc[j], sB = csrc[j + 1];
            float4 eA = ex4[j], eB = ex4[j + 1];
            float4 hA = *(const float4*)&h[(size_t)sA * 128 + lane * 4];
            float4 hB = *(const float4*)&h[(size_t)sB * 128 + lane * 4];
            float evA = lane < 16 ? (lane < 8 ? eA.x : eA.y) : (lane < 24 ? eA.z : eA.w);
            float evB = lane < 16 ? (lane < 8 ? eB.x : eB.y) : (lane < 24 ? eB.z : eB.w);
            acc.x += hA.x * evA + hB.x * evB;
            acc.y += hA.y * evA + hB.y * evB;
            acc.z += hA.z * evA + hB.z * evB;
            acc.w += hA.w * evA + hB.w * evB;
        }
        if (j < end) {
            int sA = csrc[j];
            float4 eA = ex4[j];
            float4 hA = *(const float4*)&h[(size_t)sA * 128 + lane * 4];
            float evA = lane < 16 ? (lane < 8 ? eA.x : eA.y) : (lane < 24 ? eA.z : eA.w);
            acc.x += hA.x * evA; acc.y += hA.y * evA;
            acc.z += hA.z * evA; acc.w += hA.w * evA;
        }
        float4 bi = active ? *(const float4*)&bias[lane * 4]
                           : make_float4(0.f, 0.f, 0.f, 0.f);
        float4 ov;
        ov.x = acc.x * rv + bi.x;
        ov.y = acc.y * rv + bi.y;
        ov.z = acc.z * rv + bi.z;
        ov.w = acc.w * rv + bi.w;
        if (active) *(float4*)&out[(size_t)node * 128 + lane * 4] = ov;

        if (STATS) {
            if (active) {
                int ch = lane * 4;
                atomicAdd(&sred[ch + 0], ov.x);
                atomicAdd(&sred[ch + 1], ov.y);
                atomicAdd(&sred[ch + 2], ov.z);
                atomicAdd(&sred[ch + 3], ov.w);
                atomicAdd(&sred[HD_ + ch + 0], ov.x * ov.x);
                atomicAdd(&sred[HD_ + ch + 1], ov.y * ov.y);
                atomicAdd(&sred[HD_ + ch + 2], ov.z * ov.z);
                atomicAdd(&sred[HD_ + ch + 3], ov.w * ov.w);
            }
            __syncthreads();
            if (t < 2 * HD_) atomicAdd(&bn[t], sred[t]);
        }
    } else {
        float r0 = 1.f / (s0 + 1e-16f);
        float2 acc = make_float2(0.f, 0.f);
        int j = beg;
        for (; j + 2 <= end; j += 2) {
            int sA = csrc[j], sB = csrc[j + 1];
            float eA = ex4[j].x, eB = ex4[j + 1].x;
            float2 hA = *(const float2*)&h[(size_t)sA * 64 + lane * 2];
            float2 hB = *(const float2*)&h[(size_t)sB * 64 + lane * 2];
            acc.x += hA.x * eA + hB.x * eB;
            acc.y += hA.y * eA + hB.y * eB;
        }
        if (j < end) {
            int sA = csrc[j];
            float eA = ex4[j].x;
            float2 hA = *(const float2*)&h[(size_t)sA * 64 + lane * 2];
            acc.x += hA.x * eA;
            acc.y += hA.y * eA;
        }
        if (active) {
            float2 bi = *(const float2*)&bias[lane * 2];
            float2 ov;
            ov.x = acc.x * r0 + bi.x;
            ov.y = acc.y * r0 + bi.y;
            *(float2*)&out[(size_t)node * 64 + lane * 2] = ov;
        }
    }
}

__global__ void bn_finalize(float* __restrict__ bn, const float* __restrict__ g,
                            const float* __restrict__ be) {
    int j = threadIdx.x;
    float mu = bn[j] / (float)NN;
    float var = bn[HD_ + j] / (float)NN - mu * mu;
    float sc = __ldg(&g[j]) * rsqrtf(var + 1e-5f);
    bn[2 * HD_ + j] = sc;
    bn[3 * HD_ + j] = __ldg(&be[j]) - mu * sc;
}

// ---------------- global mean pool ----------------
__global__ void pool_acc(const float* __restrict__ v, const int* __restrict__ bid,
                         float* __restrict__ pool) {
    int idx = blockIdx.x * blockDim.x + threadIdx.x;
    if (idx >= NN * OUTC) return;
    int n = idx >> 6, j = idx & 63;
    int g = __ldg(&bid[n]);
    atomicAdd(&pool[g * OUTC + j], v[(size_t)n * OUTC + j]);
}

__global__ void cnt_acc(const int* __restrict__ bid, float* __restrict__ cnt) {
    int n = blockIdx.x * blockDim.x + threadIdx.x;
    if (n >= NN) return;
    atomicAdd(&cnt[__ldg(&bid[n])], 1.f);
}

__global__ void pool_fin(const float* __restrict__ pool, const float* __restrict__ cnt,
                         float* __restrict__ out) {
    int i = blockIdx.x * blockDim.x + threadIdx.x;
    if (i >= NGRP * OUTC) return;
    float c = cnt[i >> 6];
    out[i] = pool[i] / fmaxf(c, 1.f);
}

// ---------------- host ----------------
extern "C" void kernel_launch(void* const* d_in, const int* in_sizes, int n_in,
                              void* d_out, int out_size) {
    const float* x   = (const float*)d_in[0];
    const int*   ei  = (const int*)d_in[1];
    const int*   bid = (const int*)d_in[2];
    const float *W[4], *As[4], *Ad[4], *B[4];
    for (int i = 0; i < 4; i++) {
        W[i]  = (const float*)d_in[3 + 4 * i];
        As[i] = (const float*)d_in[4 + 4 * i];
        Ad[i] = (const float*)d_in[5 + 4 * i];
        B[i]  = (const float*)d_in[6 + 4 * i];
    }
    const float *G[3], *Be[3];
    for (int i = 0; i < 3; i++) {
        G[i]  = (const float*)d_in[19 + 2 * i];
        Be[i] = (const float*)d_in[20 + 2 * i];
    }
    int E  = in_sizes[1] / 2;
    int ET = E + NN;

    float *h_, *agg_, *als_, *ald_, *bn_, *pool_, *cnt_;
    float4* ex4_;
    int *deg_, *roff_, *cur_, *csrc_;
    cudaGetSymbolAddress((void**)&h_,    g_h);
    cudaGetSymbolAddress((void**)&agg_,  g_agg);
    cudaGetSymbolAddress((void**)&als_,  g_als);
    cudaGetSymbolAddress((void**)&ald_,  g_ald);
    cudaGetSymbolAddress((void**)&ex4_,  g_ex4);
    cudaGetSymbolAddress((void**)&deg_,  g_deg);
    cudaGetSymbolAddress((void**)&roff_, g_roff);
    cudaGetSymbolAddress((void**)&cur_,  g_cur);
    cudaGetSymbolAddress((void**)&csrc_, g_csrc);
    cudaGetSymbolAddress((void**)&bn_,   g_bn);
    cudaGetSymbolAddress((void**)&pool_, g_pool);
    cudaGetSymbolAddress((void**)&cnt_,  g_cnt);

    const int TB = 256;
    const int AGG_BLOCKS = ceil_div(NN * 32, TB);  // exact: 6250

    // ---- CSR build ----
    clear_i<<<128, TB>>>(deg_, NN);
    hist_k<<<1024, TB>>>(ei, deg_, E, ET);
    scan_k<<<1, 1024>>>(deg_, roff_, cur_);
    scatter_k<<<1024, TB>>>(ei, cur_, csrc_, E, ET);

    // ---- layer 0 ----
    gemm_k<128, false><<<ceil_div(NN, 32), 128>>>(x, W[0], bn_, h_, NN);
    attn_k<4, 32><<<ceil_div(NN * 4, TB), TB>>>(h_, As[0], Ad[0], als_, ald_);
    clear_f<<<1, 256>>>(bn_, 2 * HD_);
    aggregate_k<4, 128, true><<<AGG_BLOCKS, TB>>>(roff_, csrc_, h_, als_, ald_, B[0],
                                                  ex4_, agg_, bn_);
    bn_finalize<<<1, HD_>>>(bn_, G[0], Be[0]);

    // ---- layers 1,2 ----
    for (int l = 1; l < 3; l++) {
        gemm_k<128, true><<<ceil_div(NN, 32), 128>>>(agg_, W[l], bn_, h_, NN);
        attn_k<4, 32><<<ceil_div(NN * 4, TB), TB>>>(h_, As[l], Ad[l], als_, ald_);
        clear_f<<<1, 256>>>(bn_, 2 * HD_);
        aggregate_k<4, 128, true><<<AGG_BLOCKS, TB>>>(roff_, csrc_, h_, als_, ald_, B[l],
                                                      ex4_, agg_, bn_);
        bn_finalize<<<1, HD_>>>(bn_, G[l], Be[l]);
    }

    // ---- layer 3 (H=1, OUT=64), input = elu(bn(agg)) fused into gemm ----
    gemm_k<64, true><<<ceil_div(NN, 32), 64>>>(agg_, W[3], bn_, h_, NN);
    attn_k<1, 64><<<ceil_div(NN, TB), TB>>>(h_, As[3], Ad[3], als_, ald_);
    aggregate_k<1, 64, false><<<AGG_BLOCKS, TB>>>(roff_, csrc_, h_, als_, ald_, B[3],
                                                  ex4_, agg_, bn_);

    // ---- global mean pool ----
    clear_f<<<1, 256>>>(pool_, NGRP * OUTC);
    clear_f<<<1, NGRP>>>(cnt_, NGRP);
    pool_acc<<<ceil_div(NN * OUTC, TB), TB>>>(agg_, bid, pool_);
    cnt_acc<<<ceil_div(NN, TB), TB>>>(bid, cnt_);
    pool_fin<<<ceil_div(NGRP * OUTC, TB), TB>>>(pool_, cnt_, (float*)d_out);
}